// round 15
// baseline (speedup 1.0000x reference)
#include <cuda_runtime.h>
#include <cuda_fp16.h>
#include <math.h>
#include <stdint.h>

#define BATCH   16
#define SEQ     1024
#define DIM     512
#define NHEAD   16
#define KDIM    32
#define VDIM    128
#define QKVD    192
#define QKV_OUT 3072
#define OUT_DIM 2048
#define MROWS   16384
#define ATT_SCALE 0.17677669529663687f
#define LOG2E     1.4426950408889634f

// ---------------- scratch ----------------
__device__ float  g_qkv [(size_t)MROWS * QKV_OUT];
__device__ __half g_bias[(size_t)NHEAD * SEQ * SEQ];
__device__ __half g_x   [(size_t)MROWS * DIM];
__device__ __half g_w1  [(size_t)QKV_OUT * DIM];
__device__ __half g_w2  [(size_t)DIM * OUT_DIM];
__device__ __half g_qh  [(size_t)BATCH * NHEAD * SEQ * KDIM];
__device__ __half g_ql  [(size_t)BATCH * NHEAD * SEQ * KDIM];
__device__ __half g_k   [(size_t)BATCH * NHEAD * SEQ * KDIM];
__device__ __half g_vt  [(size_t)BATCH * NHEAD * VDIM * SEQ];
__device__ __half g_ao  [(size_t)MROWS * OUT_DIM];

// ---------------- helpers ----------------
__device__ __forceinline__ uint32_t pack_h2(float lo, float hi) {
    uint32_t d;
    asm("cvt.rn.f16x2.f32 %0, %1, %2;" : "=r"(d) : "f"(hi), "f"(lo));
    return d;
}
__device__ __forceinline__ void split2h(float x, float y, uint32_t& hi, uint32_t& lo) {
    hi = pack_h2(x, y);
    __half2 h = *reinterpret_cast<__half2*>(&hi);
    lo = pack_h2(x - __half2float(h.x), y - __half2float(h.y));
}
__device__ __forceinline__ uint32_t ex2h2(uint32_t x) {
    uint32_t r;
    asm("ex2.approx.f16x2 %0, %1;" : "=r"(r) : "r"(x));
    return r;
}
__device__ __forceinline__ void mma16816h(float* c, const uint32_t* a, const uint32_t* b) {
    asm volatile(
        "mma.sync.aligned.m16n8k16.row.col.f32.f16.f16.f32 "
        "{%0,%1,%2,%3}, {%4,%5,%6,%7}, {%8,%9}, {%0,%1,%2,%3};"
        : "+f"(c[0]), "+f"(c[1]), "+f"(c[2]), "+f"(c[3])
        : "r"(a[0]), "r"(a[1]), "r"(a[2]), "r"(a[3]), "r"(b[0]), "r"(b[1]));
}
__device__ __forceinline__ void ldm_x4(uint32_t* r, uint32_t addr) {
    asm volatile("ldmatrix.sync.aligned.m8n8.x4.shared.b16 {%0,%1,%2,%3}, [%4];"
        : "=r"(r[0]), "=r"(r[1]), "=r"(r[2]), "=r"(r[3]) : "r"(addr));
}
__device__ __forceinline__ uint32_t smem_u32(const void* p) {
    uint32_t a;
    asm("{ .reg .u64 t; cvta.to.shared.u64 t, %1; cvt.u32.u64 %0, t; }" : "=r"(a) : "l"(p));
    return a;
}
__device__ __forceinline__ void cpa16(uint32_t dst, const void* src) {
    asm volatile("cp.async.cg.shared.global [%0], [%1], 16;" :: "r"(dst), "l"(src));
}
#define CP_COMMIT() asm volatile("cp.async.commit_group;" ::: "memory")
#define CP_WAIT1()  asm volatile("cp.async.wait_group 1;" ::: "memory")
#define CP_WAIT2()  asm volatile("cp.async.wait_group 2;" ::: "memory")

// ============================================================
// LayerNorm -> fp16
// ============================================================
__global__ void ln_kernel(const float* __restrict__ x,
                          const float* __restrict__ gamma,
                          const float* __restrict__ beta) {
    int row = blockIdx.x;
    int t = threadIdx.x;  // 128
    const float4* xr = reinterpret_cast<const float4*>(x + (size_t)row * DIM);
    float4 v = xr[t];
    float s = v.x + v.y + v.z + v.w;
    __shared__ float red1[4];
    __shared__ float red2[4];
    #pragma unroll
    for (int o = 16; o > 0; o >>= 1) s += __shfl_xor_sync(0xffffffffu, s, o);
    if ((t & 31) == 0) red1[t >> 5] = s;
    __syncthreads();
    float mean = (red1[0] + red1[1] + red1[2] + red1[3]) * (1.0f / DIM);
    float4 d = make_float4(v.x - mean, v.y - mean, v.z - mean, v.w - mean);
    float vs = d.x*d.x + d.y*d.y + d.z*d.z + d.w*d.w;
    #pragma unroll
    for (int o = 16; o > 0; o >>= 1) vs += __shfl_xor_sync(0xffffffffu, vs, o);
    if ((t & 31) == 0) red2[t >> 5] = vs;
    __syncthreads();
    float var = (red2[0] + red2[1] + red2[2] + red2[3]) * (1.0f / DIM);
    float rs = rsqrtf(var + 1e-5f);
    float4 g  = reinterpret_cast<const float4*>(gamma)[t];
    float4 bb = reinterpret_cast<const float4*>(beta)[t];
    float o0 = d.x * rs * g.x + bb.x;
    float o1 = d.y * rs * g.y + bb.y;
    float o2 = d.z * rs * g.z + bb.z;
    float o3 = d.w * rs * g.w + bb.w;
    size_t base = (size_t)row * DIM + t * 4;
    *(uint2*)(g_x + base) = make_uint2(pack_h2(o0, o1), pack_h2(o2, o3));
}

// ============================================================
// Weight -> fp16
// ============================================================
__global__ void w_half_kernel(const float* __restrict__ w,
                              __half* __restrict__ o) {
    int i = blockIdx.x * 256 + threadIdx.x;
    float4 v = reinterpret_cast<const float4*>(w)[i];
    *(uint2*)(o + (size_t)i * 4) = make_uint2(pack_h2(v.x, v.y), pack_h2(v.z, v.w));
}

// ============================================================
// bias pre-gather (log2e folded, fp16 output)
// ============================================================
__global__ void bias_pre_kernel(const float* __restrict__ ab,
                                const int* __restrict__ bidx) {
    __shared__ float tbl[SEQ];
    int q = blockIdx.x, h = blockIdx.y, t = threadIdx.x;
    #pragma unroll
    for (int i = 0; i < 4; i++) tbl[t + 256 * i] = ab[h * SEQ + t + 256 * i] * LOG2E;
    __syncthreads();
    int4 idx = *(const int4*)(bidx + (size_t)q * SEQ + 4 * t);
    uint32_t p0 = pack_h2(tbl[idx.x], tbl[idx.y]);
    uint32_t p1 = pack_h2(tbl[idx.z], tbl[idx.w]);
    *(uint2*)(g_bias + ((size_t)h * SEQ + q) * SEQ + 4 * t) = make_uint2(p0, p1);
}

// ============================================================
// qkv split/transpose: q -> split fp16 (scaled), k -> fp16, vT -> fp16
// ============================================================
__global__ void qkv_split_kernel(const float* __restrict__ qkv) {
    __shared__ __half sVH[128 * 72];
    int t = threadIdx.x;
    int n0 = blockIdx.x * 64, h = blockIdx.y, b = blockIdx.z;
    size_t bh = (size_t)b * NHEAD + h;
    const float QSC = ATT_SCALE * LOG2E;

    #pragma unroll
    for (int j = 0; j < 8; j++) {
        int id = t + 256 * j;
        int r = id >> 5, c = (id & 31) * 2;
        float2 v = *(const float2*)(qkv + ((size_t)((b * SEQ + n0 + r) * NHEAD + h)) * QKVD + c);
        if (c < 32) {
            uint32_t hi, lo;
            split2h(v.x * QSC, v.y * QSC, hi, lo);
            size_t o = (bh * SEQ + n0 + r) * KDIM + c;
            *(uint32_t*)(g_qh + o) = hi;
            *(uint32_t*)(g_ql + o) = lo;
        } else {
            size_t o = (bh * SEQ + n0 + r) * KDIM + (c - 32);
            *(uint32_t*)(g_k + o) = pack_h2(v.x, v.y);
        }
    }
    #pragma unroll
    for (int j = 0; j < 16; j++) {
        int id = t + 256 * j;
        int r = id >> 6, c = (id & 63) * 2;
        float2 v = *(const float2*)(qkv + ((size_t)((b * SEQ + n0 + r) * NHEAD + h)) * QKVD + 2 * KDIM + c);
        sVH[c * 72 + r]       = __float2half(v.x);
        sVH[(c + 1) * 72 + r] = __float2half(v.y);
    }
    __syncthreads();
    #pragma unroll
    for (int j = 0; j < 4; j++) {
        int id = t + 256 * j;
        int r = id >> 3, cj = (id & 7) * 8;
        size_t o = (bh * VDIM + r) * SEQ + n0 + cj;
        *(uint4*)(g_vt + o) = *(const uint4*)(sVH + r * 72 + cj);
    }
}

// ============================================================
// HMMA GEMM: C = A[M,K] @ B[N,K]^T + bias, single fp16 operands,
// 128x128 tile, BK=32, 3-stage cp.async, ldmatrix, 1 sync/iter.
// stage bytes: A +0 (128x40) | B +10240 ; stride 20480
// ============================================================
__device__ __forceinline__ void gemm_issue_stage(
    uint32_t sb_u32, int stage, int kc,
    const __half* A, const __half* B,
    int m0, int n0, int K, int t)
{
    uint32_t base = sb_u32 + stage * 20480;
    #pragma unroll
    for (int j = 0; j < 2; j++) {
        int id = t + 256 * j;
        int r = id >> 2, c = (id & 3) * 8;
        uint32_t so = (r * 40 + c) * 2;
        size_t ga = (size_t)(m0 + r) * K + kc * 32 + c;
        size_t gb = (size_t)(n0 + r) * K + kc * 32 + c;
        cpa16(base + so,         A + ga);
        cpa16(base + 10240 + so, B + gb);
    }
}

__global__ __launch_bounds__(256)
void gemm_h_kernel(const __half* __restrict__ A, const __half* __restrict__ B,
                   const float* __restrict__ bias, float* __restrict__ C,
                   int M, int N, int K)
{
    extern __shared__ __align__(16) char smc[];
    uint32_t sb_u32 = smem_u32(smc);

    const int t = threadIdx.x;
    const int m0 = blockIdx.x * 128, n0 = blockIdx.y * 128;
    const int lane = t & 31, warp = t >> 5;
    const int g = lane >> 2, tid4 = lane & 3;
    const int wm = warp >> 2, wn = warp & 3;

    const int ar_part = (lane & 7) + 8 * ((lane >> 3) & 1);
    const int ac_part = 8 * (lane >> 4);
    const int br_part = 8 * (lane >> 4) + (lane & 7);
    const int bc_part = 8 * ((lane >> 3) & 1);

    float acc[4][4][4];
    #pragma unroll
    for (int a = 0; a < 4; a++)
        #pragma unroll
        for (int bq = 0; bq < 4; bq++)
            #pragma unroll
            for (int e = 0; e < 4; e++) acc[a][bq][e] = 0.f;

    int nk = K >> 5;
    gemm_issue_stage(sb_u32, 0, 0, A, B, m0, n0, K, t);
    CP_COMMIT();
    gemm_issue_stage(sb_u32, 1, 1, A, B, m0, n0, K, t);
    CP_COMMIT();

    for (int kc = 0; kc < nk; kc++) {
        CP_WAIT1();
        __syncthreads();
        if (kc + 2 < nk)
            gemm_issue_stage(sb_u32, (kc + 2) % 3, kc + 2, A, B, m0, n0, K, t);
        CP_COMMIT();

        uint32_t st = sb_u32 + (kc % 3) * 20480;
        #pragma unroll
        for (int kt2 = 0; kt2 < 2; kt2++) {
            uint32_t ah[4][4];
            #pragma unroll
            for (int mt = 0; mt < 4; mt++) {
                uint32_t aaddr = st + ((64 * wm + 16 * mt + ar_part) * 40 + 16 * kt2 + ac_part) * 2;
                ldm_x4(ah[mt], aaddr);
            }
            #pragma unroll
            for (int jj = 0; jj < 2; jj++) {
                uint32_t baddr = st + 10240 +
                    ((32 * wn + 16 * jj + br_part) * 40 + 16 * kt2 + bc_part) * 2;
                uint32_t bh[4];
                ldm_x4(bh, baddr);
                #pragma unroll
                for (int mt = 0; mt < 4; mt++) {
                    mma16816h(acc[mt][2*jj],   ah[mt], bh);
                    mma16816h(acc[mt][2*jj+1], ah[mt], bh + 2);
                }
            }
        }
    }

    #pragma unroll
    for (int mt = 0; mt < 4; mt++) {
        int row = m0 + 64 * wm + 16 * mt + g;
        #pragma unroll
        for (int nt = 0; nt < 4; nt++) {
            int col = n0 + 32 * wn + 8 * nt + 2 * tid4;
            float2 bv = *(const float2*)(bias + col);
            float2 v0 = make_float2(acc[mt][nt][0] + bv.x, acc[mt][nt][1] + bv.y);
            float2 v1 = make_float2(acc[mt][nt][2] + bv.x, acc[mt][nt][3] + bv.y);
            *(float2*)(C + (size_t)row * N + col)       = v0;
            *(float2*)(C + (size_t)(row + 8) * N + col) = v1;
        }
    }
}

// ============================================================
// HMMA flash attention: fp16, q 2-term, k/v/p single-term,
// f16x2 ex2 softmax, bias-in-accumulator, ones-MMA row sums,
// 4-stage cp.async, ONE sync per iter, 2 blocks/SM.
// smem bytes: QH 0 | QL 5120 | stage s at 10240+s*23552:
//   K +0 (64x40) | V +5120 (128x72)
// ============================================================
#define A_STS_B 23552
#define A_NST   4

__device__ __forceinline__ void attn_issue_stage(
    uint32_t sb_u32, int stage, int k0, size_t bh, int t)
{
    uint32_t base = sb_u32 + 10240 + stage * A_STS_B;
    #pragma unroll
    for (int j = 0; j < 2; j++) {
        int id = t + 128 * j;
        int r = id >> 2, c = (id & 3) * 8;
        uint32_t so = (r * 40 + c) * 2;
        size_t gk = (bh * SEQ + k0 + r) * KDIM + c;
        cpa16(base + so, g_k + gk);
    }
    #pragma unroll
    for (int j = 0; j < 8; j++) {
        int id = t + 128 * j;
        int r = id >> 3, c = (id & 7) * 8;
        uint32_t so = (r * 72 + c) * 2;
        size_t gv = (bh * VDIM + r) * SEQ + k0 + c;
        cpa16(base + 5120 + so, g_vt + gv);
    }
}

__global__ __launch_bounds__(128, 2)
void attn_mma_kernel() {
    extern __shared__ __align__(16) char smc[];
    uint32_t sb_u32 = smem_u32(smc);

    const int t = threadIdx.x, lane = t & 31, warp = t >> 5;
    const int g = lane >> 2, tid4 = lane & 3;
    const int qb = blockIdx.x, b = blockIdx.y, h = blockIdx.z;
    const int q0 = qb * 64;
    const size_t bh = (size_t)b * NHEAD + h;

    const int qr_part = 16 * warp + (lane & 7) + 8 * ((lane >> 3) & 1);
    const int qc_part = 8 * (lane >> 4);
    const int kr_part = 8 * (lane >> 4) + (lane & 7);
    const int kc_part = 8 * ((lane >> 3) & 1);
    const int vr_part = lane & 7;
    const int vc_part = 8 * (lane >> 3);

    // prologue: Q + K/V stage 0 (group 0), stages 1, 2 (groups 1, 2)
    #pragma unroll
    for (int j = 0; j < 2; j++) {
        int id = t + 128 * j;
        int r = id >> 2, c = (id & 3) * 8;
        uint32_t so = (r * 40 + c) * 2;
        size_t gq = (bh * SEQ + q0 + r) * KDIM + c;
        cpa16(sb_u32 + so,        g_qh + gq);
        cpa16(sb_u32 + 5120 + so, g_ql + gq);
    }
    attn_issue_stage(sb_u32, 0, 0, bh, t);
    CP_COMMIT();
    attn_issue_stage(sb_u32, 1, 64, bh, t);
    CP_COMMIT();
    attn_issue_stage(sb_u32, 2, 128, bh, t);
    CP_COMMIT();

    CP_WAIT2();
    __syncthreads();
    uint32_t qa_h[2][4], qa_l[2][4];
    {
        uint32_t qaddr = sb_u32 + (qr_part * 40 + qc_part) * 2;
        ldm_x4(qa_h[0], qaddr);
        ldm_x4(qa_h[1], qaddr + 32);
        ldm_x4(qa_l[0], qaddr + 5120);
        ldm_x4(qa_l[1], qaddr + 5120 + 32);
    }

    float o[16][4];
    #pragma unroll
    for (int nt = 0; nt < 16; nt++)
        #pragma unroll
        for (int e = 0; e < 4; e++) o[nt][e] = 0.f;
    float lacc[4] = {0.f, 0.f, 0.f, 0.f};       // row sums via ones-MMA
    const uint32_t ones_b[2] = {0x3C003C00u, 0x3C003C00u};
    const int r0 = q0 + 16 * warp + g;
    const int r1 = r0 + 8;
    const __half* bbase0 = g_bias + ((size_t)h * SEQ + r0) * SEQ + 2 * tid4;
    const __half* bbase1 = g_bias + ((size_t)h * SEQ + r1) * SEQ + 2 * tid4;

    for (int it = 0; it < 16; it++) {
        CP_WAIT2();
        __syncthreads();
        if (it + 3 < 16)
            attn_issue_stage(sb_u32, (it + 3) % A_NST, (it + 3) * 64, bh, t);
        CP_COMMIT();

        const int k0 = it * 64;
        uint32_t sK = sb_u32 + 10240 + (it % A_NST) * A_STS_B;
        uint32_t sV = sK + 5120;

        // ---- QK accumulators initialized with bias (free add) ----
        float s[8][4];
        #pragma unroll
        for (int j = 0; j < 8; j++) {
            float2 b0v = __half22float2(*(const __half2*)(bbase0 + k0 + 8 * j));
            float2 b1v = __half22float2(*(const __half2*)(bbase1 + k0 + 8 * j));
            s[j][0] = b0v.x; s[j][1] = b0v.y;
            s[j][2] = b1v.x; s[j][3] = b1v.y;
        }
        #pragma unroll
        for (int kt2 = 0; kt2 < 2; kt2++) {
            #pragma unroll
            for (int jj = 0; jj < 4; jj++) {
                uint32_t kaddr = sK + ((16 * jj + kr_part) * 40 + 16 * kt2 + kc_part) * 2;
                uint32_t kh[4];
                ldm_x4(kh, kaddr);
                mma16816h(s[2*jj],   qa_h[kt2], kh);
                mma16816h(s[2*jj],   qa_l[kt2], kh);
                mma16816h(s[2*jj+1], qa_h[kt2], kh + 2);
                mma16816h(s[2*jj+1], qa_l[kt2], kh + 2);
            }
        }

        // ---- f16x2 ex2 softmax (p direct to fp16 frags) ----
        uint32_t pa[4][4];
        #pragma unroll
        for (int j = 0; j < 8; j++) {
            pa[j >> 1][(j & 1) * 2 + 0] = ex2h2(pack_h2(s[j][0], s[j][1]));
            pa[j >> 1][(j & 1) * 2 + 1] = ex2h2(pack_h2(s[j][2], s[j][3]));
        }

        // ---- row sums on the tensor pipe: lacc += pa[u] @ ones ----
        #pragma unroll
        for (int u = 0; u < 4; u++)
            mma16816h(lacc, pa[u], ones_b);

        // ---- PV ----
        #pragma unroll
        for (int nt = 0; nt < 16; nt++) {
            uint32_t vaddr = sV + ((8 * nt + vr_part) * 72 + vc_part) * 2;
            uint32_t vh[8];
            ldm_x4(vh,     vaddr);
            ldm_x4(vh + 4, vaddr + 64);
            #pragma unroll
            for (int u = 0; u < 4; u++)
                mma16816h(o[nt], pa[u], vh + 2 * u);
        }
    }

    float i0 = 1.f / lacc[0], i1 = 1.f / lacc[2];
    #pragma unroll
    for (int nt = 0; nt < 16; nt++) {
        int col = h * VDIM + 8 * nt + 2 * tid4;
        size_t o0 = (size_t)(b * SEQ + r0) * OUT_DIM + col;
        size_t o1 = (size_t)(b * SEQ + r1) * OUT_DIM + col;
        *(uint32_t*)(g_ao + o0) = pack_h2(o[nt][0] * i0, o[nt][1] * i0);
        *(uint32_t*)(g_ao + o1) = pack_h2(o[nt][2] * i1, o[nt][3] * i1);
    }
}

// ============================================================
// launch
// ============================================================
extern "C" void kernel_launch(void* const* d_in, const int* in_sizes, int n_in,
                              void* d_out, int out_size) {
    const float* x     = (const float*)d_in[0];
    const float* gamma = (const float*)d_in[1];
    const float* beta  = (const float*)d_in[2];
    const float* Wqkv  = (const float*)d_in[3];
    const float* bqkv  = (const float*)d_in[4];
    const float* Wproj = (const float*)d_in[5];
    const float* bproj = (const float*)d_in[6];
    const float* ab    = (const float*)d_in[7];
    const int*   bidx  = (const int*)d_in[8];
    float* out = (float*)d_out;

    void *pqkv, *px, *pw1, *pw2, *pao;
    cudaGetSymbolAddress(&pqkv, g_qkv);
    cudaGetSymbolAddress(&px, g_x);
    cudaGetSymbolAddress(&pw1, g_w1);
    cudaGetSymbolAddress(&pw2, g_w2);
    cudaGetSymbolAddress(&pao, g_ao);

    const int gemm_smem = 3 * 20480;                 // 61440 B
    const int attn_smem = 10240 + A_NST * A_STS_B;   // 104448 B
    cudaFuncSetAttribute(gemm_h_kernel,
                         cudaFuncAttributeMaxDynamicSharedMemorySize, gemm_smem);
    cudaFuncSetAttribute(attn_mma_kernel,
                         cudaFuncAttributeMaxDynamicSharedMemorySize, attn_smem);

    ln_kernel<<<MROWS, 128>>>(x, gamma, beta);
    w_half_kernel<<<(QKV_OUT * DIM / 4) / 256, 256>>>(Wqkv, (__half*)pw1);
    w_half_kernel<<<(DIM * OUT_DIM / 4) / 256, 256>>>(Wproj, (__half*)pw2);
    bias_pre_kernel<<<dim3(SEQ, NHEAD), 256>>>(ab, bidx);

    gemm_h_kernel<<<dim3(MROWS / 128, QKV_OUT / 128), 256, gemm_smem>>>(
        (const __half*)px, (const __half*)pw1,
        bqkv, (float*)pqkv, MROWS, QKV_OUT, DIM);

    qkv_split_kernel<<<dim3(SEQ / 64, NHEAD, BATCH), 256>>>((const float*)pqkv);

    attn_mma_kernel<<<dim3(SEQ / 64, BATCH, NHEAD), 128, attn_smem>>>();

    gemm_h_kernel<<<dim3(MROWS / 128, DIM / 128), 256, gemm_smem>>>(
        (const __half*)pao, (const __half*)pw2,
        bproj, out, MROWS, DIM, OUT_DIM);
}

// round 17
// speedup vs baseline: 1.1201x; 1.1201x over previous
#include <cuda_runtime.h>
#include <cuda_fp16.h>
#include <math.h>
#include <stdint.h>

#define BATCH   16
#define SEQ     1024
#define DIM     512
#define NHEAD   16
#define KDIM    32
#define VDIM    128
#define QKVD    192
#define QKV_OUT 3072
#define OUT_DIM 2048
#define MROWS   16384
#define ATT_SCALE 0.17677669529663687f
#define LOG2E     1.4426950408889634f
#define QSC       (ATT_SCALE * LOG2E)

// ---------------- scratch ----------------
__device__ __half g_bias[(size_t)NHEAD * SEQ * SEQ];
__device__ __half g_x   [(size_t)MROWS * DIM];
__device__ __half g_w1  [(size_t)QKV_OUT * DIM];
__device__ __half g_w2  [(size_t)DIM * OUT_DIM];
__device__ __half g_qkvh[(size_t)MROWS * QKV_OUT];   // 96 MB, q pre-scaled
__device__ __half g_ao  [(size_t)MROWS * OUT_DIM];

// ---------------- helpers ----------------
__device__ __forceinline__ uint32_t pack_h2(float lo, float hi) {
    uint32_t d;
    asm("cvt.rn.f16x2.f32 %0, %1, %2;" : "=r"(d) : "f"(hi), "f"(lo));
    return d;
}
__device__ __forceinline__ uint32_t ex2h2(uint32_t x) {
    uint32_t r;
    asm("ex2.approx.f16x2 %0, %1;" : "=r"(r) : "r"(x));
    return r;
}
__device__ __forceinline__ void mma16816h(float* c, const uint32_t* a, const uint32_t* b) {
    asm volatile(
        "mma.sync.aligned.m16n8k16.row.col.f32.f16.f16.f32 "
        "{%0,%1,%2,%3}, {%4,%5,%6,%7}, {%8,%9}, {%0,%1,%2,%3};"
        : "+f"(c[0]), "+f"(c[1]), "+f"(c[2]), "+f"(c[3])
        : "r"(a[0]), "r"(a[1]), "r"(a[2]), "r"(a[3]), "r"(b[0]), "r"(b[1]));
}
__device__ __forceinline__ void ldm_x4(uint32_t* r, uint32_t addr) {
    asm volatile("ldmatrix.sync.aligned.m8n8.x4.shared.b16 {%0,%1,%2,%3}, [%4];"
        : "=r"(r[0]), "=r"(r[1]), "=r"(r[2]), "=r"(r[3]) : "r"(addr));
}
__device__ __forceinline__ void ldm_x4t(uint32_t* r, uint32_t addr) {
    asm volatile("ldmatrix.sync.aligned.m8n8.x4.trans.shared.b16 {%0,%1,%2,%3}, [%4];"
        : "=r"(r[0]), "=r"(r[1]), "=r"(r[2]), "=r"(r[3]) : "r"(addr));
}
__device__ __forceinline__ uint32_t smem_u32(const void* p) {
    uint32_t a;
    asm("{ .reg .u64 t; cvta.to.shared.u64 t, %1; cvt.u32.u64 %0, t; }" : "=r"(a) : "l"(p));
    return a;
}
__device__ __forceinline__ void cpa16(uint32_t dst, const void* src) {
    asm volatile("cp.async.cg.shared.global [%0], [%1], 16;" :: "r"(dst), "l"(src));
}
#define CP_COMMIT() asm volatile("cp.async.commit_group;" ::: "memory")
#define CP_WAIT1()  asm volatile("cp.async.wait_group 1;" ::: "memory")
#define CP_WAIT2()  asm volatile("cp.async.wait_group 2;" ::: "memory")

// ============================================================
// LayerNorm -> fp16
// ============================================================
__global__ void ln_kernel(const float* __restrict__ x,
                          const float* __restrict__ gamma,
                          const float* __restrict__ beta) {
    int row = blockIdx.x;
    int t = threadIdx.x;  // 128
    const float4* xr = reinterpret_cast<const float4*>(x + (size_t)row * DIM);
    float4 v = xr[t];
    float s = v.x + v.y + v.z + v.w;
    __shared__ float red1[4];
    __shared__ float red2[4];
    #pragma unroll
    for (int o = 16; o > 0; o >>= 1) s += __shfl_xor_sync(0xffffffffu, s, o);
    if ((t & 31) == 0) red1[t >> 5] = s;
    __syncthreads();
    float mean = (red1[0] + red1[1] + red1[2] + red1[3]) * (1.0f / DIM);
    float4 d = make_float4(v.x - mean, v.y - mean, v.z - mean, v.w - mean);
    float vs = d.x*d.x + d.y*d.y + d.z*d.z + d.w*d.w;
    #pragma unroll
    for (int o = 16; o > 0; o >>= 1) vs += __shfl_xor_sync(0xffffffffu, vs, o);
    if ((t & 31) == 0) red2[t >> 5] = vs;
    __syncthreads();
    float var = (red2[0] + red2[1] + red2[2] + red2[3]) * (1.0f / DIM);
    float rs = rsqrtf(var + 1e-5f);
    float4 g  = reinterpret_cast<const float4*>(gamma)[t];
    float4 bb = reinterpret_cast<const float4*>(beta)[t];
    float o0 = d.x * rs * g.x + bb.x;
    float o1 = d.y * rs * g.y + bb.y;
    float o2 = d.z * rs * g.z + bb.z;
    float o3 = d.w * rs * g.w + bb.w;
    size_t base = (size_t)row * DIM + t * 4;
    *(uint2*)(g_x + base) = make_uint2(pack_h2(o0, o1), pack_h2(o2, o3));
}

// ============================================================
// Weight -> fp16
// ============================================================
__global__ void w_half_kernel(const float* __restrict__ w,
                              __half* __restrict__ o) {
    int i = blockIdx.x * 256 + threadIdx.x;
    float4 v = reinterpret_cast<const float4*>(w)[i];
    *(uint2*)(o + (size_t)i * 4) = make_uint2(pack_h2(v.x, v.y), pack_h2(v.z, v.w));
}

// ============================================================
// bias pre-gather (log2e folded, fp16 output)
// ============================================================
__global__ void bias_pre_kernel(const float* __restrict__ ab,
                                const int* __restrict__ bidx) {
    __shared__ float tbl[SEQ];
    int q = blockIdx.x, h = blockIdx.y, t = threadIdx.x;
    #pragma unroll
    for (int i = 0; i < 4; i++) tbl[t + 256 * i] = ab[h * SEQ + t + 256 * i] * LOG2E;
    __syncthreads();
    int4 idx = *(const int4*)(bidx + (size_t)q * SEQ + 4 * t);
    uint32_t p0 = pack_h2(tbl[idx.x], tbl[idx.y]);
    uint32_t p1 = pack_h2(tbl[idx.z], tbl[idx.w]);
    *(uint2*)(g_bias + ((size_t)h * SEQ + q) * SEQ + 4 * t) = make_uint2(p0, p1);
}

// ============================================================
// GEMM core (shared): 128x128 tile, BK=32, 3-stage cp.async,
// ldmatrix, 1 sync/iter.
// stage bytes: A +0 (128x40) | B +10240 ; stride 20480
// ============================================================
__device__ __forceinline__ void gemm_issue_stage(
    uint32_t sb_u32, int stage, int kc,
    const __half* A, const __half* B,
    int m0, int n0, int K, int t)
{
    uint32_t base = sb_u32 + stage * 20480;
    #pragma unroll
    for (int j = 0; j < 2; j++) {
        int id = t + 256 * j;
        int r = id >> 2, c = (id & 3) * 8;
        uint32_t so = (r * 40 + c) * 2;
        size_t ga = (size_t)(m0 + r) * K + kc * 32 + c;
        size_t gb = (size_t)(n0 + r) * K + kc * 32 + c;
        cpa16(base + so,         A + ga);
        cpa16(base + 10240 + so, B + gb);
    }
}

#define GEMM_MAIN_BODY(ACC)                                                     \
    int nk = K >> 5;                                                            \
    gemm_issue_stage(sb_u32, 0, 0, A, B, m0, n0, K, t);                         \
    CP_COMMIT();                                                                \
    gemm_issue_stage(sb_u32, 1, 1, A, B, m0, n0, K, t);                         \
    CP_COMMIT();                                                                \
    for (int kc = 0; kc < nk; kc++) {                                           \
        CP_WAIT1();                                                             \
        __syncthreads();                                                        \
        if (kc + 2 < nk)                                                        \
            gemm_issue_stage(sb_u32, (kc + 2) % 3, kc + 2, A, B, m0, n0, K, t); \
        CP_COMMIT();                                                            \
        uint32_t st = sb_u32 + (kc % 3) * 20480;                                \
        _Pragma("unroll")                                                       \
        for (int kt2 = 0; kt2 < 2; kt2++) {                                     \
            uint32_t ah[4][4];                                                  \
            _Pragma("unroll")                                                   \
            for (int mt = 0; mt < 4; mt++) {                                    \
                uint32_t aaddr = st + ((64 * wm + 16 * mt + ar_part) * 40       \
                                       + 16 * kt2 + ac_part) * 2;               \
                ldm_x4(ah[mt], aaddr);                                          \
            }                                                                   \
            _Pragma("unroll")                                                   \
            for (int jj = 0; jj < 2; jj++) {                                    \
                uint32_t baddr = st + 10240 +                                   \
                    ((32 * wn + 16 * jj + br_part) * 40 + 16 * kt2 + bc_part) * 2; \
                uint32_t bh[4];                                                 \
                ldm_x4(bh, baddr);                                              \
                _Pragma("unroll")                                               \
                for (int mt = 0; mt < 4; mt++) {                                \
                    mma16816h(ACC[mt][2*jj],   ah[mt], bh);                     \
                    mma16816h(ACC[mt][2*jj+1], ah[mt], bh + 2);                 \
                }                                                               \
            }                                                                   \
        }                                                                       \
    }

// ---- fp32-out GEMM (proj) ----
__global__ __launch_bounds__(256)
void gemm_h_kernel(const __half* __restrict__ A, const __half* __restrict__ B,
                   const float* __restrict__ bias, float* __restrict__ C,
                   int M, int N, int K)
{
    extern __shared__ __align__(16) char smc[];
    uint32_t sb_u32 = smem_u32(smc);
    const int t = threadIdx.x;
    const int m0 = blockIdx.x * 128, n0 = blockIdx.y * 128;
    const int lane = t & 31, warp = t >> 5;
    const int g = lane >> 2, tid4 = lane & 3;
    const int wm = warp >> 2, wn = warp & 3;
    const int ar_part = (lane & 7) + 8 * ((lane >> 3) & 1);
    const int ac_part = 8 * (lane >> 4);
    const int br_part = 8 * (lane >> 4) + (lane & 7);
    const int bc_part = 8 * ((lane >> 3) & 1);

    float acc[4][4][4];
    #pragma unroll
    for (int a = 0; a < 4; a++)
        #pragma unroll
        for (int bq = 0; bq < 4; bq++)
            #pragma unroll
            for (int e = 0; e < 4; e++) acc[a][bq][e] = 0.f;

    GEMM_MAIN_BODY(acc)

    #pragma unroll
    for (int mt = 0; mt < 4; mt++) {
        int row = m0 + 64 * wm + 16 * mt + g;
        #pragma unroll
        for (int nt = 0; nt < 4; nt++) {
            int col = n0 + 32 * wn + 8 * nt + 2 * tid4;
            float2 bv = *(const float2*)(bias + col);
            float2 v0 = make_float2(acc[mt][nt][0] + bv.x, acc[mt][nt][1] + bv.y);
            float2 v1 = make_float2(acc[mt][nt][2] + bv.x, acc[mt][nt][3] + bv.y);
            *(float2*)(C + (size_t)row * N + col)       = v0;
            *(float2*)(C + (size_t)(row + 8) * N + col) = v1;
        }
    }
}

// ---- fp16-out GEMM with q-column pre-scale (QKV) ----
__global__ __launch_bounds__(256)
void gemm_hq_kernel(const __half* __restrict__ A, const __half* __restrict__ B,
                    const float* __restrict__ bias, __half* __restrict__ C,
                    int M, int N, int K)
{
    extern __shared__ __align__(16) char smc[];
    uint32_t sb_u32 = smem_u32(smc);
    const int t = threadIdx.x;
    const int m0 = blockIdx.x * 128, n0 = blockIdx.y * 128;
    const int lane = t & 31, warp = t >> 5;
    const int g = lane >> 2, tid4 = lane & 3;
    const int wm = warp >> 2, wn = warp & 3;
    const int ar_part = (lane & 7) + 8 * ((lane >> 3) & 1);
    const int ac_part = 8 * (lane >> 4);
    const int br_part = 8 * (lane >> 4) + (lane & 7);
    const int bc_part = 8 * ((lane >> 3) & 1);

    float acc[4][4][4];
    #pragma unroll
    for (int a = 0; a < 4; a++)
        #pragma unroll
        for (int bq = 0; bq < 4; bq++)
            #pragma unroll
            for (int e = 0; e < 4; e++) acc[a][bq][e] = 0.f;

    GEMM_MAIN_BODY(acc)

    #pragma unroll
    for (int mt = 0; mt < 4; mt++) {
        int row = m0 + 64 * wm + 16 * mt + g;
        #pragma unroll
        for (int nt = 0; nt < 4; nt++) {
            int col = n0 + 32 * wn + 8 * nt + 2 * tid4;
            float2 bv = *(const float2*)(bias + col);
            float qs = ((col % QKVD) < KDIM) ? QSC : 1.0f;   // pair never straddles
            uint32_t v0 = pack_h2((acc[mt][nt][0] + bv.x) * qs,
                                  (acc[mt][nt][1] + bv.y) * qs);
            uint32_t v1 = pack_h2((acc[mt][nt][2] + bv.x) * qs,
                                  (acc[mt][nt][3] + bv.y) * qs);
            *(uint32_t*)(C + (size_t)row * N + col)       = v0;
            *(uint32_t*)(C + (size_t)(row + 8) * N + col) = v1;
        }
    }
}

// ============================================================
// HMMA flash attention: fp16, q/k/v/p single-term, f16x2 ex2,
// staging direct from qkv (V untransposed + ldmatrix.trans),
// 4-stage cp.async, ONE sync per iter, 2 blocks/SM.
// smem bytes: Q 0 (64x40 = 5120) | stage s at 5120+s*22528:
//   K +0 (64x40 = 5120) | V +5120 (64x136 = 17408)
// ============================================================
#define A_STS_B 22528
#define A_NST   4
#define VROW    136

__device__ __forceinline__ void attn_issue_stage(
    uint32_t sb_u32, int stage, int k0, size_t bseq_h, int t)
{
    uint32_t base = sb_u32 + 5120 + stage * A_STS_B;
    #pragma unroll
    for (int j = 0; j < 2; j++) {      // K: 64 rows x 32 halves
        int id = t + 128 * j;
        int r = id >> 2, c = (id & 3) * 8;
        const __half* src = g_qkvh + (bseq_h + (size_t)(k0 + r) * QKV_OUT) + KDIM + c;
        cpa16(base + (r * 40 + c) * 2, src);
    }
    #pragma unroll
    for (int j = 0; j < 8; j++) {      // V: 64 rows x 128 halves
        int id = t + 128 * j;
        int r = id >> 4, c = (id & 15) * 8;
        const __half* src = g_qkvh + (bseq_h + (size_t)(k0 + r) * QKV_OUT) + 2 * KDIM + c;
        cpa16(base + 5120 + (r * VROW + c) * 2, src);   // V at byte +5120
    }
}

__global__ __launch_bounds__(128, 2)
void attn_mma_kernel() {
    extern __shared__ __align__(16) char smc[];
    uint32_t sb_u32 = smem_u32(smc);

    const int t = threadIdx.x, lane = t & 31, warp = t >> 5;
    const int g = lane >> 2, tid4 = lane & 3;
    const int qb = blockIdx.x, b = blockIdx.y, h = blockIdx.z;
    const int q0 = qb * 64;
    const size_t bseq_h = ((size_t)b * SEQ) * QKV_OUT + (size_t)h * QKVD;

    const int qr_part = 16 * warp + (lane & 7) + 8 * ((lane >> 3) & 1);
    const int qc_part = 8 * (lane >> 4);
    const int kr_part = 8 * (lane >> 4) + (lane & 7);
    const int kc_part = 8 * ((lane >> 3) & 1);

    // prologue: Q (group 0 with stage 0) + stages 1, 2
    #pragma unroll
    for (int j = 0; j < 2; j++) {
        int id = t + 128 * j;
        int r = id >> 2, c = (id & 3) * 8;
        const __half* src = g_qkvh + (bseq_h + (size_t)(q0 + r) * QKV_OUT) + c;
        cpa16(sb_u32 + (r * 40 + c) * 2, src);
    }
    attn_issue_stage(sb_u32, 0, 0, bseq_h, t);
    CP_COMMIT();
    attn_issue_stage(sb_u32, 1, 64, bseq_h, t);
    CP_COMMIT();
    attn_issue_stage(sb_u32, 2, 128, bseq_h, t);
    CP_COMMIT();

    CP_WAIT2();
    __syncthreads();
    uint32_t qa[2][4];
    {
        uint32_t qaddr = sb_u32 + (qr_part * 40 + qc_part) * 2;
        ldm_x4(qa[0], qaddr);
        ldm_x4(qa[1], qaddr + 32);
    }

    float o[16][4];
    #pragma unroll
    for (int nt = 0; nt < 16; nt++)
        #pragma unroll
        for (int e = 0; e < 4; e++) o[nt][e] = 0.f;
    float lsum0 = 0.f, lsum1 = 0.f;
    const int r0 = q0 + 16 * warp + g;
    const int r1 = r0 + 8;
    const __half* bbase0 = g_bias + ((size_t)h * SEQ + r0) * SEQ + 2 * tid4;
    const __half* bbase1 = g_bias + ((size_t)h * SEQ + r1) * SEQ + 2 * tid4;

    for (int it = 0; it < 16; it++) {
        CP_WAIT2();
        __syncthreads();
        if (it + 3 < 16)
            attn_issue_stage(sb_u32, (it + 3) % A_NST, (it + 3) * 64, bseq_h, t);
        CP_COMMIT();

        const int k0 = it * 64;
        uint32_t sK = sb_u32 + 5120 + (it % A_NST) * A_STS_B;
        uint32_t sV = sK + 5120;

        // prefetch bias (fp16 -> fp32 regs; hides LDG behind QK MMAs)
        float2 b0v[8], b1v[8];
        #pragma unroll
        for (int j = 0; j < 8; j++) {
            b0v[j] = __half22float2(*(const __half2*)(bbase0 + k0 + 8 * j));
            b1v[j] = __half22float2(*(const __half2*)(bbase1 + k0 + 8 * j));
        }

        // ---- QK (q single-term) ----
        float s[8][4];
        #pragma unroll
        for (int j = 0; j < 8; j++)
            #pragma unroll
            for (int e = 0; e < 4; e++) s[j][e] = 0.f;
        #pragma unroll
        for (int kt2 = 0; kt2 < 2; kt2++) {
            #pragma unroll
            for (int jj = 0; jj < 4; jj++) {
                uint32_t kaddr = sK + ((16 * jj + kr_part) * 40 + 16 * kt2 + kc_part) * 2;
                uint32_t kh[4];
                ldm_x4(kh, kaddr);
                mma16816h(s[2*jj],   qa[kt2], kh);
                mma16816h(s[2*jj+1], qa[kt2], kh + 2);
            }
        }

        // ---- f16x2 ex2 softmax ----
        uint32_t pa[4][4];
        #pragma unroll
        for (int j = 0; j < 8; j++) {
            uint32_t e01 = ex2h2(pack_h2(s[j][0] + b0v[j].x, s[j][1] + b0v[j].y));
            uint32_t e23 = ex2h2(pack_h2(s[j][2] + b1v[j].x, s[j][3] + b1v[j].y));
            pa[j >> 1][(j & 1) * 2 + 0] = e01;
            pa[j >> 1][(j & 1) * 2 + 1] = e23;
            float2 f01 = __half22float2(*reinterpret_cast<__half2*>(&e01));
            float2 f23 = __half22float2(*reinterpret_cast<__half2*>(&e23));
            lsum0 += f01.x + f01.y;
            lsum1 += f23.x + f23.y;
        }

        // ---- PV: V [key][vcol] via ldmatrix.trans ----
        #pragma unroll
        for (int nt = 0; nt < 16; nt++) {
            uint32_t vaddr = sV + (lane * VROW + 8 * nt) * 2;
            uint32_t vh[8];
            ldm_x4t(vh,     vaddr);
            ldm_x4t(vh + 4, vaddr + 32 * VROW * 2);
            #pragma unroll
            for (int u = 0; u < 4; u++)
                mma16816h(o[nt], pa[u], vh + 2 * u);
        }
    }

    lsum0 += __shfl_xor_sync(0xffffffffu, lsum0, 1);
    lsum0 += __shfl_xor_sync(0xffffffffu, lsum0, 2);
    lsum1 += __shfl_xor_sync(0xffffffffu, lsum1, 1);
    lsum1 += __shfl_xor_sync(0xffffffffu, lsum1, 2);
    float i0 = 1.f / lsum0, i1 = 1.f / lsum1;
    #pragma unroll
    for (int nt = 0; nt < 16; nt++) {
        int col = h * VDIM + 8 * nt + 2 * tid4;
        size_t o0 = (size_t)(b * SEQ + r0) * OUT_DIM + col;
        size_t o1 = (size_t)(b * SEQ + r1) * OUT_DIM + col;
        *(uint32_t*)(g_ao + o0) = pack_h2(o[nt][0] * i0, o[nt][1] * i0);
        *(uint32_t*)(g_ao + o1) = pack_h2(o[nt][2] * i1, o[nt][3] * i1);
    }
}

// ============================================================
// launch
// ============================================================
extern "C" void kernel_launch(void* const* d_in, const int* in_sizes, int n_in,
                              void* d_out, int out_size) {
    const float* x     = (const float*)d_in[0];
    const float* gamma = (const float*)d_in[1];
    const float* beta  = (const float*)d_in[2];
    const float* Wqkv  = (const float*)d_in[3];
    const float* bqkv  = (const float*)d_in[4];
    const float* Wproj = (const float*)d_in[5];
    const float* bproj = (const float*)d_in[6];
    const float* ab    = (const float*)d_in[7];
    const int*   bidx  = (const int*)d_in[8];
    float* out = (float*)d_out;

    void *px, *pw1, *pw2, *pqkvh, *pao;
    cudaGetSymbolAddress(&px, g_x);
    cudaGetSymbolAddress(&pw1, g_w1);
    cudaGetSymbolAddress(&pw2, g_w2);
    cudaGetSymbolAddress(&pqkvh, g_qkvh);
    cudaGetSymbolAddress(&pao, g_ao);

    const int gemm_smem = 3 * 20480;               // 61440 B
    const int attn_smem = 5120 + A_NST * A_STS_B;  // 95232 B
    cudaFuncSetAttribute(gemm_h_kernel,
                         cudaFuncAttributeMaxDynamicSharedMemorySize, gemm_smem);
    cudaFuncSetAttribute(gemm_hq_kernel,
                         cudaFuncAttributeMaxDynamicSharedMemorySize, gemm_smem);
    cudaFuncSetAttribute(attn_mma_kernel,
                         cudaFuncAttributeMaxDynamicSharedMemorySize, attn_smem);

    ln_kernel<<<MROWS, 128>>>(x, gamma, beta);
    w_half_kernel<<<(QKV_OUT * DIM / 4) / 256, 256>>>(Wqkv, (__half*)pw1);
    w_half_kernel<<<(DIM * OUT_DIM / 4) / 256, 256>>>(Wproj, (__half*)pw2);
    bias_pre_kernel<<<dim3(SEQ, NHEAD), 256>>>(ab, bidx);

    gemm_hq_kernel<<<dim3(MROWS / 128, QKV_OUT / 128), 256, gemm_smem>>>(
        (const __half*)px, (const __half*)pw1,
        bqkv, (__half*)pqkvh, MROWS, QKV_OUT, DIM);

    attn_mma_kernel<<<dim3(SEQ / 64, BATCH, NHEAD), 128, attn_smem>>>();

    gemm_h_kernel<<<dim3(MROWS / 128, DIM / 128), 256, gemm_smem>>>(
        (const __half*)pao, (const __half*)pw2,
        bproj, out, MROWS, DIM, OUT_DIM);
}